// round 1
// baseline (speedup 1.0000x reference)
#include <cuda_runtime.h>
#include <cuda_bf16.h>
#include <math.h>

// ---------------- Problem constants ----------------
#define BB 16
#define SS 256
#define HH 768
#define LL 12
#define AH 12
#define DH 64
#define FF 3072
#define NL 9
#define NT (BB*SS)           // 4096 tokens
#define NBH (BB*AH)          // 192 batch*head

typedef long long ll;

// ---------------- Device scratch (static, allocation-free) ----------------
__device__ float g_x  [NT*HH];
__device__ float g_q  [NT*HH];
__device__ float g_k  [NT*HH];
__device__ float g_v  [NT*HH];
__device__ float g_ctx[NT*HH];
__device__ float g_tmp[NT*HH];
__device__ float g_h  [NT*FF];
__device__ float g_sc [NBH*SS*SS];
__device__ float g_vo [NT*HH];

// ---------------- Block reduction (256 threads) ----------------
template<bool MAXR>
__device__ __forceinline__ float block_reduce(float v) {
    __shared__ float sh[33];
    int lane = threadIdx.x & 31, w = threadIdx.x >> 5;
    #pragma unroll
    for (int o = 16; o; o >>= 1) {
        float t = __shfl_xor_sync(0xffffffffu, v, o);
        v = MAXR ? fmaxf(v, t) : (v + t);
    }
    if (lane == 0) sh[w] = v;
    __syncthreads();
    if (w == 0) {
        int nw = blockDim.x >> 5;
        float t = (lane < nw) ? sh[lane] : (MAXR ? -3.4e38f : 0.f);
        #pragma unroll
        for (int o = 16; o; o >>= 1) {
            float u = __shfl_xor_sync(0xffffffffu, t, o);
            t = MAXR ? fmaxf(t, u) : (t + u);
        }
        if (lane == 0) sh[32] = t;
    }
    __syncthreads();
    float r = sh[32];
    __syncthreads();
    return r;
}

// ---------------- Generic tiled GEMM ----------------
// C[z] = act( A[z] * B[z] (+bias) )
// A: [M,K] (row stride lda). B: [K,N] row-major if !TB, else [N,K] (B^T view).
// Batch offsets: ptr + (z/div)*s1 + (z%div)*s2.
template<int BM,int BN,int BK,int TM,int TN,bool TB,int ACT>
__global__ void __launch_bounds__((BM/TM)*(BN/TN))
gemm_kernel(const float* __restrict__ A, const float* __restrict__ B,
            const float* __restrict__ bias, float* __restrict__ C,
            int M, int N, int K, int lda, int ldb, int ldc,
            int divA, ll sA1, ll sA2,
            int divB, ll sB1, ll sB2,
            int divC, ll sC1, ll sC2)
{
    constexpr int THREADS = (BM/TM)*(BN/TN);
    constexpr int NX = BN/TN;
    __shared__ __align__(16) float As[BK][BM];
    __shared__ __align__(16) float Bs[BK][BN];

    int z = blockIdx.z;
    const float* Ab = A + (ll)(z / divA) * sA1 + (ll)(z % divA) * sA2;
    const float* Bb = B + (ll)(z / divB) * sB1 + (ll)(z % divB) * sB2;
    float*       Cb = C + (ll)(z / divC) * sC1 + (ll)(z % divC) * sC2;

    int tm0 = blockIdx.y * BM, tn0 = blockIdx.x * BN;
    int tid = threadIdx.x;
    int tx = tid % NX, ty = tid / NX;

    float acc[TM][TN];
    #pragma unroll
    for (int i = 0; i < TM; i++)
        #pragma unroll
        for (int j = 0; j < TN; j++) acc[i][j] = 0.f;

    for (int k0 = 0; k0 < K; k0 += BK) {
        #pragma unroll
        for (int i = tid; i < BM*BK; i += THREADS) {
            int m = i / BK, kk = i % BK;
            As[kk][m] = Ab[(ll)(tm0 + m) * lda + (k0 + kk)];
        }
        if (!TB) {
            #pragma unroll
            for (int i = tid; i < BK*BN; i += THREADS) {
                int kk = i / BN, n = i % BN;
                Bs[kk][n] = Bb[(ll)(k0 + kk) * ldb + (tn0 + n)];
            }
        } else {
            #pragma unroll
            for (int i = tid; i < BK*BN; i += THREADS) {
                int n = i / BK, kk = i % BK;
                Bs[kk][n] = Bb[(ll)(tn0 + n) * ldb + (k0 + kk)];
            }
        }
        __syncthreads();

        #pragma unroll
        for (int kk = 0; kk < BK; kk++) {
            float ra[TM], rb[TN];
            #pragma unroll
            for (int i = 0; i < TM; i += 4) {
                float4 t = *(const float4*)&As[kk][ty*TM + i];
                ra[i] = t.x; ra[i+1] = t.y; ra[i+2] = t.z; ra[i+3] = t.w;
            }
            #pragma unroll
            for (int j = 0; j < TN; j += 4) {
                float4 t = *(const float4*)&Bs[kk][tx*TN + j];
                rb[j] = t.x; rb[j+1] = t.y; rb[j+2] = t.z; rb[j+3] = t.w;
            }
            #pragma unroll
            for (int i = 0; i < TM; i++)
                #pragma unroll
                for (int j = 0; j < TN; j++)
                    acc[i][j] = fmaf(ra[i], rb[j], acc[i][j]);
        }
        __syncthreads();
    }

    #pragma unroll
    for (int i = 0; i < TM; i++) {
        int m = tm0 + ty*TM + i;
        #pragma unroll
        for (int j = 0; j < TN; j++) {
            int n = tn0 + tx*TN + j;
            float vv = acc[i][j];
            if (bias) vv += bias[n];
            if (ACT == 1) {
                float c = vv;
                vv = 0.5f * c * (1.f + tanhf(0.7978845608028654f * (c + 0.044715f * c*c*c)));
            }
            Cb[(ll)m * ldc + n] = vv;
        }
    }
}

template<int BM,int BN,int BK,int TM,int TN,bool TB,int ACT>
static void gemm_launch(const float* A, const float* B, const float* bias, float* C,
                        int M, int N, int K, int lda, int ldb, int ldc, int batches,
                        int divA, ll sA1, ll sA2,
                        int divB, ll sB1, ll sB2,
                        int divC, ll sC1, ll sC2)
{
    dim3 grid(N/BN, M/BM, batches);
    dim3 block((BM/TM)*(BN/TN));
    gemm_kernel<BM,BN,BK,TM,TN,TB,ACT><<<grid, block>>>(
        A, B, bias, C, M, N, K, lda, ldb, ldc,
        divA, sA1, sA2, divB, sB1, sB2, divC, sC1, sC2);
}

// ---------------- Embedding + LayerNorm ----------------
__global__ void embed_ln_kernel(const int* __restrict__ ids, const int* __restrict__ types,
                                const float* __restrict__ wemb, const float* __restrict__ pemb,
                                const float* __restrict__ temb,
                                const float* __restrict__ g, const float* __restrict__ b,
                                float* __restrict__ x)
{
    int tok = blockIdx.x;
    int s = tok % SS;
    int t = threadIdx.x;
    int id = ids[tok];
    int ty = types[tok];
    float v[3];
    float sum = 0.f;
    #pragma unroll
    for (int i = 0; i < 3; i++) {
        int h = t + i*256;
        float val = wemb[(ll)id*HH + h] + pemb[s*HH + h] + temb[ty*HH + h];
        v[i] = val; sum += val;
    }
    float mean = block_reduce<false>(sum) * (1.f/HH);
    float sq = 0.f;
    #pragma unroll
    for (int i = 0; i < 3; i++) { float d = v[i] - mean; sq += d*d; }
    float var = block_reduce<false>(sq) * (1.f/HH);
    float rstd = rsqrtf(var + 1e-12f);
    #pragma unroll
    for (int i = 0; i < 3; i++) {
        int h = t + i*256;
        x[(ll)tok*HH + h] = (v[i] - mean) * rstd * g[h] + b[h];
    }
}

// ---------------- Residual add + LayerNorm (in-place safe per-row) ----------------
__global__ void add_ln_kernel(const float* __restrict__ xin, const float* __restrict__ tmp,
                              const float* __restrict__ g, const float* __restrict__ b,
                              float* __restrict__ xout)
{
    int tok = blockIdx.x;
    int t = threadIdx.x;
    float v[3];
    float sum = 0.f;
    #pragma unroll
    for (int i = 0; i < 3; i++) {
        int h = t + i*256;
        float val = xin[(ll)tok*HH + h] + tmp[(ll)tok*HH + h];
        v[i] = val; sum += val;
    }
    float mean = block_reduce<false>(sum) * (1.f/HH);
    float sq = 0.f;
    #pragma unroll
    for (int i = 0; i < 3; i++) { float d = v[i] - mean; sq += d*d; }
    float var = block_reduce<false>(sq) * (1.f/HH);
    float rstd = rsqrtf(var + 1e-12f);
    #pragma unroll
    for (int i = 0; i < 3; i++) {
        int h = t + i*256;
        xout[(ll)tok*HH + h] = (v[i] - mean) * rstd * g[h] + b[h];
    }
}

// ---------------- Attention softmax (scale + mask + softmax per row) ----------------
__global__ void attn_softmax_kernel(float* __restrict__ sc, const int* __restrict__ mask)
{
    ll row = blockIdx.x;              // 0 .. NBH*SS-1
    int t = threadIdx.x;              // 256 = key index
    int bh = (int)(row >> 8);         // row / SS
    int b = bh / AH;
    float* p = sc + row * SS;
    float madd = mask[b*SS + t] ? 0.f : -10000.f;
    float v = p[t] * 0.125f + madd;   // 1/sqrt(64)
    float mx = block_reduce<true>(v);
    float e = expf(v - mx);
    float s = block_reduce<false>(e);
    p[t] = e / s;
}

// ---------------- Valid-token compaction ----------------
__global__ void compact_kernel(const float* __restrict__ x, const int* __restrict__ valid,
                               float* __restrict__ vo)
{
    int b = blockIdx.x;
    int t = threadIdx.x;
    __shared__ int vload[SS];
    __shared__ int rank[SS];
    vload[t] = valid[b*SS + t];
    __syncthreads();
    int r = 0;
    for (int i = 0; i < t; i++) r += vload[i];
    rank[t] = r;
    __syncthreads();
    float* vob = vo + (ll)b * SS * HH;
    for (int i = t; i < SS*HH; i += 256) vob[i] = 0.f;
    __syncthreads();
    int w = t >> 5, lane = t & 31;
    for (int s = w; s < SS; s += 8) {
        if (vload[s]) {
            const float* src = x + ((ll)b*SS + s) * HH;
            float* dst = vob + (ll)rank[s] * HH;
            for (int i = lane; i < HH; i += 32) dst[i] = src[i];
        }
    }
}

// ---------------- Classifier head: logits + softmax over 9 classes ----------------
__global__ void cls_kernel(const float* __restrict__ vo, const float* __restrict__ W,
                           const float* __restrict__ bias, float* __restrict__ out)
{
    int tok = blockIdx.x;
    int t = threadIdx.x;
    const float* v = vo + (ll)tok * HH;
    float acc[NL];
    #pragma unroll
    for (int j = 0; j < NL; j++) acc[j] = 0.f;
    for (int i = t; i < HH; i += 256) {
        float xv = v[i];
        const float* w = W + (ll)i * NL;
        #pragma unroll
        for (int j = 0; j < NL; j++) acc[j] += xv * w[j];
    }
    __shared__ float red[NL*256];
    #pragma unroll
    for (int j = 0; j < NL; j++) red[j*256 + t] = acc[j];
    __syncthreads();
    for (int o = 128; o; o >>= 1) {
        if (t < o) {
            #pragma unroll
            for (int j = 0; j < NL; j++) red[j*256 + t] += red[j*256 + t + o];
        }
        __syncthreads();
    }
    if (t == 0) {
        float lg[NL];
        float mx = -3.4e38f;
        #pragma unroll
        for (int j = 0; j < NL; j++) { lg[j] = red[j*256] + bias[j]; mx = fmaxf(mx, lg[j]); }
        float s = 0.f;
        #pragma unroll
        for (int j = 0; j < NL; j++) { lg[j] = expf(lg[j] - mx); s += lg[j]; }
        float inv = 1.f / s;
        #pragma unroll
        for (int j = 0; j < NL; j++) out[(ll)tok*NL + j] = lg[j] * inv;
    }
}

// ---------------- Launch orchestration ----------------
extern "C" void kernel_launch(void* const* d_in, const int* in_sizes, int n_in,
                              void* d_out, int out_size)
{
    const int*   ids   = (const int*)  d_in[0];
    const int*   imask = (const int*)  d_in[1];
    const int*   types = (const int*)  d_in[2];
    const int*   vmask = (const int*)  d_in[3];
    const float* wemb  = (const float*)d_in[4];
    const float* pemb  = (const float*)d_in[5];
    const float* temb  = (const float*)d_in[6];
    const float* eg    = (const float*)d_in[7];
    const float* eb    = (const float*)d_in[8];
    const float* Wq    = (const float*)d_in[9];
    const float* bq    = (const float*)d_in[10];
    const float* Wk    = (const float*)d_in[11];
    const float* bk    = (const float*)d_in[12];
    const float* Wv    = (const float*)d_in[13];
    const float* bv    = (const float*)d_in[14];
    const float* Wo    = (const float*)d_in[15];
    const float* bo    = (const float*)d_in[16];
    const float* ag    = (const float*)d_in[17];
    const float* ab    = (const float*)d_in[18];
    const float* W1    = (const float*)d_in[19];
    const float* b1    = (const float*)d_in[20];
    const float* W2    = (const float*)d_in[21];
    const float* b2    = (const float*)d_in[22];
    const float* fg    = (const float*)d_in[23];
    const float* fb    = (const float*)d_in[24];
    const float* cW    = (const float*)d_in[25];
    const float* cb    = (const float*)d_in[26];
    float* out = (float*)d_out;

    float *x, *q, *k, *v, *ctx, *tmp, *hbuf, *sc, *vo;
    cudaGetSymbolAddress((void**)&x,    g_x);
    cudaGetSymbolAddress((void**)&q,    g_q);
    cudaGetSymbolAddress((void**)&k,    g_k);
    cudaGetSymbolAddress((void**)&v,    g_v);
    cudaGetSymbolAddress((void**)&ctx,  g_ctx);
    cudaGetSymbolAddress((void**)&tmp,  g_tmp);
    cudaGetSymbolAddress((void**)&hbuf, g_h);
    cudaGetSymbolAddress((void**)&sc,   g_sc);
    cudaGetSymbolAddress((void**)&vo,   g_vo);

    // 1) embeddings + LN
    embed_ln_kernel<<<NT, 256>>>(ids, types, wemb, pemb, temb, eg, eb, x);

    // 2) transformer layers
    for (int l = 0; l < LL; l++) {
        const float* wq = Wq + (ll)l*HH*HH;  const float* bql = bq + (ll)l*HH;
        const float* wk = Wk + (ll)l*HH*HH;  const float* bkl = bk + (ll)l*HH;
        const float* wv = Wv + (ll)l*HH*HH;  const float* bvl = bv + (ll)l*HH;
        const float* wo = Wo + (ll)l*HH*HH;  const float* bol = bo + (ll)l*HH;
        const float* w1 = W1 + (ll)l*HH*FF;  const float* b1l = b1 + (ll)l*FF;
        const float* w2 = W2 + (ll)l*FF*HH;  const float* b2l = b2 + (ll)l*HH;
        const float* agl = ag + (ll)l*HH;    const float* abl = ab + (ll)l*HH;
        const float* fgl = fg + (ll)l*HH;    const float* fbl = fb + (ll)l*HH;

        // QKV projections
        gemm_launch<128,128,8,8,8,false,0>(x, wq, bql, q, NT, HH, HH, HH, HH, HH,
                                           1, 1,0,0, 1,0,0, 1,0,0);
        gemm_launch<128,128,8,8,8,false,0>(x, wk, bkl, k, NT, HH, HH, HH, HH, HH,
                                           1, 1,0,0, 1,0,0, 1,0,0);
        gemm_launch<128,128,8,8,8,false,0>(x, wv, bvl, v, NT, HH, HH, HH, HH, HH,
                                           1, 1,0,0, 1,0,0, 1,0,0);

        // scores = Q * K^T per (b,h)
        gemm_launch<64,64,16,4,4,true,0>(q, k, nullptr, sc, SS, SS, DH, HH, HH, SS,
                                         NBH,
                                         AH, (ll)SS*HH, DH,
                                         AH, (ll)SS*HH, DH,
                                         1,  (ll)SS*SS, 0);
        // softmax with scale + mask
        attn_softmax_kernel<<<NBH*SS, 256>>>(sc, imask);
        // ctx = P * V per (b,h)
        gemm_launch<64,64,16,4,4,false,0>(sc, v, nullptr, ctx, SS, DH, SS, SS, HH, HH,
                                          NBH,
                                          1,  (ll)SS*SS, 0,
                                          AH, (ll)SS*HH, DH,
                                          AH, (ll)SS*HH, DH);
        // output projection
        gemm_launch<128,128,8,8,8,false,0>(ctx, wo, bol, tmp, NT, HH, HH, HH, HH, HH,
                                           1, 1,0,0, 1,0,0, 1,0,0);
        add_ln_kernel<<<NT, 256>>>(x, tmp, agl, abl, x);

        // FFN
        gemm_launch<128,128,8,8,8,false,1>(x, w1, b1l, hbuf, NT, FF, HH, HH, FF, FF,
                                           1, 1,0,0, 1,0,0, 1,0,0);
        gemm_launch<128,128,8,8,8,false,0>(hbuf, w2, b2l, tmp, NT, HH, FF, FF, HH, HH,
                                           1, 1,0,0, 1,0,0, 1,0,0);
        add_ln_kernel<<<NT, 256>>>(x, tmp, fgl, fbl, x);
    }

    // 3) valid-token compaction
    compact_kernel<<<BB, 256>>>(x, vmask, vo);

    // 4) classifier + softmax
    cls_kernel<<<NT, 256>>>(vo, cW, cb, out);

    (void)in_sizes; (void)n_in; (void)out_size;
}

// round 2
// speedup vs baseline: 1.1256x; 1.1256x over previous
#include <cuda_runtime.h>
#include <cuda_bf16.h>
#include <math.h>
#include <stdint.h>

// ---------------- Problem constants ----------------
#define BB 16
#define SS 256
#define HH 768
#define LL 12
#define AH 12
#define DH 64
#define FF 3072
#define NL 9
#define NT (BB*SS)           // 4096 tokens
#define NBH (BB*AH)          // 192 batch*head
#define QKVN (3*HH)          // 2304

typedef long long ll;

// ---------------- Device scratch (static, allocation-free) ----------------
__device__ float g_x   [NT*HH];
__device__ float g_qkv [NT*QKVN];
__device__ float g_ctx [NT*HH];
__device__ float g_tmp [NT*HH];
__device__ float g_h   [NT*FF];
__device__ float g_sc  [(ll)NBH*SS*SS];
__device__ float g_vo  [NT*HH];
__device__ float g_wqkv[(ll)LL*HH*QKVN];
__device__ float g_bqkv[LL*QKVN];

// ---------------- PTX helpers ----------------
__device__ __forceinline__ uint32_t f2tf(float x) {
    uint32_t u;
    asm("cvt.rna.tf32.f32 %0, %1;" : "=r"(u) : "f"(x));
    return u;
}

__device__ __forceinline__ void mma8(float c[4], const uint32_t a[4], const uint32_t b[2]) {
    asm volatile(
        "mma.sync.aligned.m16n8k8.row.col.f32.tf32.tf32.f32 "
        "{%0,%1,%2,%3}, {%4,%5,%6,%7}, {%8,%9}, {%0,%1,%2,%3};"
        : "+f"(c[0]), "+f"(c[1]), "+f"(c[2]), "+f"(c[3])
        : "r"(a[0]), "r"(a[1]), "r"(a[2]), "r"(a[3]), "r"(b[0]), "r"(b[1]));
}

__device__ __forceinline__ void cpa16(uint32_t dst, const float* src, int src_bytes) {
    asm volatile("cp.async.ca.shared.global [%0], [%1], 16, %2;"
                 :: "r"(dst), "l"(src), "r"(src_bytes));
}
__device__ __forceinline__ void cpa_commit() { asm volatile("cp.async.commit_group;"); }
__device__ __forceinline__ void cpa_wait1()  { asm volatile("cp.async.wait_group 1;"); }
__device__ __forceinline__ void cpa_wait0()  { asm volatile("cp.async.wait_group 0;"); }

// ---------------- 3xTF32 tensor-core GEMM ----------------
// C[z] = act( A[z] * B[z] (+bias) ),  fp32 in/out, 3xTF32 compensated mma.
// BM=128, BN=128, BK=16, 128 threads (4 warps, 2x2), warp tile 64x64.
// TB=false: B is [K,N] row-major.  TB=true: B is [N,K] row-major (i.e. B^T view).
template<bool TB, int ACT>
__global__ void __launch_bounds__(128)
tgemm(const float* __restrict__ A, const float* __restrict__ B,
      const float* __restrict__ bias, float* __restrict__ C,
      int M, int N, int K, int lda, int ldb, int ldc,
      int divA, ll sA1, ll sA2,
      int divB, ll sB1, ll sB2,
      int divC, ll sC1, ll sC2)
{
    constexpr int BROWS  = TB ? 128 : 16;
    constexpr int BPITCH = TB ? 20  : 136;

    __shared__ float As[2][128][20];
    __shared__ float Bs[2][BROWS][BPITCH];

    const int tid  = threadIdx.x;
    const int lane = tid & 31;
    const int wid  = tid >> 5;
    const int gid  = lane >> 2;     // 0..7
    const int tq   = lane & 3;      // 0..3
    const int wm   = wid & 1;       // warp M index (2)
    const int wn   = wid >> 1;      // warp N index (2)

    const int z = blockIdx.z;
    const float* Ab = A + (ll)(z / divA) * sA1 + (ll)(z % divA) * sA2;
    const float* Bb = B + (ll)(z / divB) * sB1 + (ll)(z % divB) * sB2;
    float*       Cb = C + (ll)(z / divC) * sC1 + (ll)(z % divC) * sC2;

    const int tm0 = blockIdx.y * 128;
    const int tn0 = blockIdx.x * 128;

    uint32_t sA = (uint32_t)__cvta_generic_to_shared(&As[0][0][0]);
    uint32_t sB = (uint32_t)__cvta_generic_to_shared(&Bs[0][0][0]);

    float c[4][8][4];
    #pragma unroll
    for (int mt = 0; mt < 4; mt++)
        #pragma unroll
        for (int nt = 0; nt < 8; nt++)
            #pragma unroll
            for (int q = 0; q < 4; q++) c[mt][nt][q] = 0.f;

    auto prefetch = [&](int s, int k0) {
        // A tile: 128 rows x 16 k, 512 16B-chunks
        #pragma unroll
        for (int j = 0; j < 4; j++) {
            int i = tid + j * 128;
            int row = i >> 2, kc = i & 3;
            uint32_t dst = sA + (uint32_t)(((s * 128 + row) * 20 + kc * 4) * 4);
            const float* src = Ab + (ll)(tm0 + row) * lda + (k0 + kc * 4);
            cpa16(dst, src, 16);
        }
        if (!TB) {
            // B tile: 16 k x 128 n
            #pragma unroll
            for (int j = 0; j < 4; j++) {
                int i = tid + j * 128;
                int kr = i >> 5, nc = i & 31;
                int n = tn0 + nc * 4;
                uint32_t dst = sB + (uint32_t)(((s * 16 + kr) * 136 + nc * 4) * 4);
                bool ok = (n < N);
                const float* src = ok ? (Bb + (ll)(k0 + kr) * ldb + n) : Bb;
                cpa16(dst, src, ok ? 16 : 0);
            }
        } else {
            // B tile (transposed view): 128 n rows x 16 k
            #pragma unroll
            for (int j = 0; j < 4; j++) {
                int i = tid + j * 128;
                int nr = i >> 2, kc = i & 3;
                int n = tn0 + nr;
                uint32_t dst = sB + (uint32_t)(((s * 128 + nr) * 20 + kc * 4) * 4);
                bool ok = (n < N);
                const float* src = ok ? (Bb + (ll)n * ldb + (k0 + kc * 4)) : Bb;
                cpa16(dst, src, ok ? 16 : 0);
            }
        }
        cpa_commit();
    };

    const int KT = K / 16;
    prefetch(0, 0);
    int s = 0;

    for (int kt = 0; kt < KT; kt++) {
        if (kt + 1 < KT) { prefetch(s ^ 1, (kt + 1) * 16); cpa_wait1(); }
        else             { cpa_wait0(); }
        __syncthreads();

        #pragma unroll
        for (int ks = 0; ks < 2; ks++) {
            const int k8 = ks * 8;
            uint32_t ah[4][4], al[4][4];
            #pragma unroll
            for (int mt = 0; mt < 4; mt++) {
                #pragma unroll
                for (int q = 0; q < 4; q++) {
                    int r  = wm * 64 + mt * 16 + gid + (q & 1) * 8;
                    int kk = k8 + tq + (q >> 1) * 4;
                    float x = As[s][r][kk];
                    uint32_t h = f2tf(x);
                    ah[mt][q] = h;
                    al[mt][q] = f2tf(x - __uint_as_float(h));
                }
            }
            #pragma unroll
            for (int nt = 0; nt < 8; nt++) {
                uint32_t bh[2], bl[2];
                #pragma unroll
                for (int q = 0; q < 2; q++) {
                    int kk  = k8 + tq + q * 4;
                    int col = wn * 64 + nt * 8 + gid;
                    float x = TB ? Bs[s][col][kk] : Bs[s][kk][col];
                    uint32_t h = f2tf(x);
                    bh[q] = h;
                    bl[q] = f2tf(x - __uint_as_float(h));
                }
                #pragma unroll
                for (int mt = 0; mt < 4; mt++) {
                    mma8(c[mt][nt], ah[mt], bh);
                    mma8(c[mt][nt], al[mt], bh);
                    mma8(c[mt][nt], ah[mt], bl);
                }
            }
        }
        __syncthreads();
        s ^= 1;
    }

    // Epilogue
    #pragma unroll
    for (int mt = 0; mt < 4; mt++) {
        int r = tm0 + wm * 64 + mt * 16 + gid;
        #pragma unroll
        for (int nt = 0; nt < 8; nt++) {
            int col = tn0 + wn * 64 + nt * 8 + tq * 2;
            if (col < N) {
                float v0 = c[mt][nt][0], v1 = c[mt][nt][1];
                float v2 = c[mt][nt][2], v3 = c[mt][nt][3];
                if (bias) {
                    float b0 = bias[col], b1 = bias[col + 1];
                    v0 += b0; v1 += b1; v2 += b0; v3 += b1;
                }
                if (ACT == 1) {
                    float t;
                    t = v0; v0 = 0.5f*t*(1.f + tanhf(0.7978845608028654f*(t + 0.044715f*t*t*t)));
                    t = v1; v1 = 0.5f*t*(1.f + tanhf(0.7978845608028654f*(t + 0.044715f*t*t*t)));
                    t = v2; v2 = 0.5f*t*(1.f + tanhf(0.7978845608028654f*(t + 0.044715f*t*t*t)));
                    t = v3; v3 = 0.5f*t*(1.f + tanhf(0.7978845608028654f*(t + 0.044715f*t*t*t)));
                }
                *(float2*)&Cb[(ll)r * ldc + col]       = make_float2(v0, v1);
                *(float2*)&Cb[(ll)(r + 8) * ldc + col] = make_float2(v2, v3);
            }
        }
    }
}

template<bool TB, int ACT>
static void tgemm_launch(const float* A, const float* B, const float* bias, float* C,
                         int M, int N, int K, int lda, int ldb, int ldc, int batches,
                         int divA, ll sA1, ll sA2,
                         int divB, ll sB1, ll sB2,
                         int divC, ll sC1, ll sC2)
{
    dim3 grid((N + 127) / 128, M / 128, batches);
    tgemm<TB, ACT><<<grid, 128>>>(A, B, bias, C, M, N, K, lda, ldb, ldc,
                                  divA, sA1, sA2, divB, sB1, sB2, divC, sC1, sC2);
}

// ---------------- QKV weight packing ----------------
__global__ void pack_qkv_kernel(const float* __restrict__ Wq, const float* __restrict__ Wk,
                                const float* __restrict__ Wv, float* __restrict__ wp)
{
    ll i = (ll)blockIdx.x * 256 + threadIdx.x;
    if (i >= (ll)LL * HH * QKVN) return;
    int l   = (int)(i / ((ll)HH * QKVN));
    int rem = (int)(i % ((ll)HH * QKVN));
    int row = rem / QKVN;
    int col = rem % QKVN;
    int sel = col / HH;
    int cc  = col % HH;
    const float* W = (sel == 0) ? Wq : (sel == 1) ? Wk : Wv;
    wp[i] = W[(ll)l * HH * HH + (ll)row * HH + cc];
}

__global__ void pack_bias_kernel(const float* __restrict__ bq, const float* __restrict__ bk,
                                 const float* __restrict__ bv, float* __restrict__ bp)
{
    int i = blockIdx.x * 256 + threadIdx.x;
    if (i >= LL * QKVN) return;
    int l = i / QKVN, col = i % QKVN;
    int sel = col / HH, cc = col % HH;
    const float* b = (sel == 0) ? bq : (sel == 1) ? bk : bv;
    bp[i] = b[l * HH + cc];
}

// ---------------- Block reduction (256 threads) ----------------
template<bool MAXR>
__device__ __forceinline__ float block_reduce(float v) {
    __shared__ float sh[33];
    int lane = threadIdx.x & 31, w = threadIdx.x >> 5;
    #pragma unroll
    for (int o = 16; o; o >>= 1) {
        float t = __shfl_xor_sync(0xffffffffu, v, o);
        v = MAXR ? fmaxf(v, t) : (v + t);
    }
    if (lane == 0) sh[w] = v;
    __syncthreads();
    if (w == 0) {
        int nw = blockDim.x >> 5;
        float t = (lane < nw) ? sh[lane] : (MAXR ? -3.4e38f : 0.f);
        #pragma unroll
        for (int o = 16; o; o >>= 1) {
            float u = __shfl_xor_sync(0xffffffffu, t, o);
            t = MAXR ? fmaxf(t, u) : (t + u);
        }
        if (lane == 0) sh[32] = t;
    }
    __syncthreads();
    float r = sh[32];
    __syncthreads();
    return r;
}

// ---------------- Embedding + LayerNorm ----------------
__global__ void embed_ln_kernel(const int* __restrict__ ids, const int* __restrict__ types,
                                const float* __restrict__ wemb, const float* __restrict__ pemb,
                                const float* __restrict__ temb,
                                const float* __restrict__ g, const float* __restrict__ b,
                                float* __restrict__ x)
{
    int tok = blockIdx.x;
    int s = tok % SS;
    int t = threadIdx.x;
    int id = ids[tok];
    int ty = types[tok];
    float v[3];
    float sum = 0.f;
    #pragma unroll
    for (int i = 0; i < 3; i++) {
        int h = t + i*256;
        float val = wemb[(ll)id*HH + h] + pemb[s*HH + h] + temb[ty*HH + h];
        v[i] = val; sum += val;
    }
    float mean = block_reduce<false>(sum) * (1.f/HH);
    float sq = 0.f;
    #pragma unroll
    for (int i = 0; i < 3; i++) { float d = v[i] - mean; sq += d*d; }
    float var = block_reduce<false>(sq) * (1.f/HH);
    float rstd = rsqrtf(var + 1e-12f);
    #pragma unroll
    for (int i = 0; i < 3; i++) {
        int h = t + i*256;
        x[(ll)tok*HH + h] = (v[i] - mean) * rstd * g[h] + b[h];
    }
}

// ---------------- Residual add + LayerNorm ----------------
__global__ void add_ln_kernel(const float* __restrict__ xin, const float* __restrict__ tmp,
                              const float* __restrict__ g, const float* __restrict__ b,
                              float* __restrict__ xout)
{
    int tok = blockIdx.x;
    int t = threadIdx.x;
    float v[3];
    float sum = 0.f;
    #pragma unroll
    for (int i = 0; i < 3; i++) {
        int h = t + i*256;
        float val = xin[(ll)tok*HH + h] + tmp[(ll)tok*HH + h];
        v[i] = val; sum += val;
    }
    float mean = block_reduce<false>(sum) * (1.f/HH);
    float sq = 0.f;
    #pragma unroll
    for (int i = 0; i < 3; i++) { float d = v[i] - mean; sq += d*d; }
    float var = block_reduce<false>(sq) * (1.f/HH);
    float rstd = rsqrtf(var + 1e-12f);
    #pragma unroll
    for (int i = 0; i < 3; i++) {
        int h = t + i*256;
        xout[(ll)tok*HH + h] = (v[i] - mean) * rstd * g[h] + b[h];
    }
}

// ---------------- Attention softmax ----------------
__global__ void attn_softmax_kernel(float* __restrict__ sc, const int* __restrict__ mask)
{
    ll row = blockIdx.x;
    int t = threadIdx.x;
    int bh = (int)(row >> 8);
    int b = bh / AH;
    float* p = sc + row * SS;
    float madd = mask[b*SS + t] ? 0.f : -10000.f;
    float v = p[t] * 0.125f + madd;
    float mx = block_reduce<true>(v);
    float e = expf(v - mx);
    float s = block_reduce<false>(e);
    p[t] = e / s;
}

// ---------------- Valid-token compaction ----------------
__global__ void compact_kernel(const float* __restrict__ x, const int* __restrict__ valid,
                               float* __restrict__ vo)
{
    int b = blockIdx.x;
    int t = threadIdx.x;
    __shared__ int vload[SS];
    __shared__ int rank[SS];
    vload[t] = valid[b*SS + t];
    __syncthreads();
    int r = 0;
    for (int i = 0; i < t; i++) r += vload[i];
    rank[t] = r;
    __syncthreads();
    float* vob = vo + (ll)b * SS * HH;
    for (int i = t; i < SS*HH; i += 256) vob[i] = 0.f;
    __syncthreads();
    int w = t >> 5, lane = t & 31;
    for (int s = w; s < SS; s += 8) {
        if (vload[s]) {
            const float* src = x + ((ll)b*SS + s) * HH;
            float* dst = vob + (ll)rank[s] * HH;
            for (int i = lane; i < HH; i += 32) dst[i] = src[i];
        }
    }
}

// ---------------- Classifier head ----------------
__global__ void cls_kernel(const float* __restrict__ vo, const float* __restrict__ W,
                           const float* __restrict__ bias, float* __restrict__ out)
{
    int tok = blockIdx.x;
    int t = threadIdx.x;
    const float* v = vo + (ll)tok * HH;
    float acc[NL];
    #pragma unroll
    for (int j = 0; j < NL; j++) acc[j] = 0.f;
    for (int i = t; i < HH; i += 256) {
        float xv = v[i];
        const float* w = W + (ll)i * NL;
        #pragma unroll
        for (int j = 0; j < NL; j++) acc[j] += xv * w[j];
    }
    __shared__ float red[NL*256];
    #pragma unroll
    for (int j = 0; j < NL; j++) red[j*256 + t] = acc[j];
    __syncthreads();
    for (int o = 128; o; o >>= 1) {
        if (t < o) {
            #pragma unroll
            for (int j = 0; j < NL; j++) red[j*256 + t] += red[j*256 + t + o];
        }
        __syncthreads();
    }
    if (t == 0) {
        float lg[NL];
        float mx = -3.4e38f;
        #pragma unroll
        for (int j = 0; j < NL; j++) { lg[j] = red[j*256] + bias[j]; mx = fmaxf(mx, lg[j]); }
        float s = 0.f;
        #pragma unroll
        for (int j = 0; j < NL; j++) { lg[j] = expf(lg[j] - mx); s += lg[j]; }
        float inv = 1.f / s;
        #pragma unroll
        for (int j = 0; j < NL; j++) out[(ll)tok*NL + j] = lg[j] * inv;
    }
}

// ---------------- Launch orchestration ----------------
extern "C" void kernel_launch(void* const* d_in, const int* in_sizes, int n_in,
                              void* d_out, int out_size)
{
    const int*   ids   = (const int*)  d_in[0];
    const int*   imask = (const int*)  d_in[1];
    const int*   types = (const int*)  d_in[2];
    const int*   vmask = (const int*)  d_in[3];
    const float* wemb  = (const float*)d_in[4];
    const float* pemb  = (const float*)d_in[5];
    const float* temb  = (const float*)d_in[6];
    const float* eg    = (const float*)d_in[7];
    const float* eb    = (const float*)d_in[8];
    const float* Wq    = (const float*)d_in[9];
    const float* bq    = (const float*)d_in[10];
    const float* Wk    = (const float*)d_in[11];
    const float* bk    = (const float*)d_in[12];
    const float* Wv    = (const float*)d_in[13];
    const float* bv    = (const float*)d_in[14];
    const float* Wo    = (const float*)d_in[15];
    const float* bo    = (const float*)d_in[16];
    const float* ag    = (const float*)d_in[17];
    const float* ab    = (const float*)d_in[18];
    const float* W1    = (const float*)d_in[19];
    const float* b1    = (const float*)d_in[20];
    const float* W2    = (const float*)d_in[21];
    const float* b2    = (const float*)d_in[22];
    const float* fg    = (const float*)d_in[23];
    const float* fb    = (const float*)d_in[24];
    const float* cW    = (const float*)d_in[25];
    const float* cb    = (const float*)d_in[26];
    float* out = (float*)d_out;

    float *x, *qkv, *ctx, *tmp, *hbuf, *sc, *vo, *wqkv, *bqkv;
    cudaGetSymbolAddress((void**)&x,    g_x);
    cudaGetSymbolAddress((void**)&qkv,  g_qkv);
    cudaGetSymbolAddress((void**)&ctx,  g_ctx);
    cudaGetSymbolAddress((void**)&tmp,  g_tmp);
    cudaGetSymbolAddress((void**)&hbuf, g_h);
    cudaGetSymbolAddress((void**)&sc,   g_sc);
    cudaGetSymbolAddress((void**)&vo,   g_vo);
    cudaGetSymbolAddress((void**)&wqkv, g_wqkv);
    cudaGetSymbolAddress((void**)&bqkv, g_bqkv);

    // 0) pack QKV weights into one [H, 3H] matrix per layer
    {
        ll total = (ll)LL * HH * QKVN;
        int blocks = (int)((total + 255) / 256);
        pack_qkv_kernel<<<blocks, 256>>>(Wq, Wk, Wv, wqkv);
        pack_bias_kernel<<<(LL*QKVN + 255)/256, 256>>>(bq, bk, bv, bqkv);
    }

    // 1) embeddings + LN
    embed_ln_kernel<<<NT, 256>>>(ids, types, wemb, pemb, temb, eg, eb, x);

    // 2) transformer layers
    for (int l = 0; l < LL; l++) {
        const float* wqkvl = wqkv + (ll)l*HH*QKVN;
        const float* bqkvl = bqkv + (ll)l*QKVN;
        const float* wo = Wo + (ll)l*HH*HH;  const float* bol = bo + (ll)l*HH;
        const float* w1 = W1 + (ll)l*HH*FF;  const float* b1l = b1 + (ll)l*FF;
        const float* w2 = W2 + (ll)l*FF*HH;  const float* b2l = b2 + (ll)l*HH;
        const float* agl = ag + (ll)l*HH;    const float* abl = ab + (ll)l*HH;
        const float* fgl = fg + (ll)l*HH;    const float* fbl = fb + (ll)l*HH;

        // fused QKV projection: [NT,768] x [768,2304]
        tgemm_launch<false,0>(x, wqkvl, bqkvl, qkv, NT, QKVN, HH, HH, QKVN, QKVN, 1,
                              1,0,0, 1,0,0, 1,0,0);

        // scores = Q * K^T per (b,h):  A rows stride 2304, B = K rows stride 2304 (TB)
        tgemm_launch<true,0>(qkv, qkv + HH, nullptr, sc, SS, SS, DH, QKVN, QKVN, SS,
                             NBH,
                             AH, (ll)SS*QKVN, DH,
                             AH, (ll)SS*QKVN, DH,
                             1,  (ll)SS*SS, 0);
        attn_softmax_kernel<<<NBH*SS, 256>>>(sc, imask);
        // ctx = P * V per (b,h)
        tgemm_launch<false,0>(sc, qkv + 2*HH, nullptr, ctx, SS, DH, SS, SS, QKVN, HH,
                              NBH,
                              1,  (ll)SS*SS, 0,
                              AH, (ll)SS*QKVN, DH,
                              AH, (ll)SS*HH, DH);
        // output projection
        tgemm_launch<false,0>(ctx, wo, bol, tmp, NT, HH, HH, HH, HH, HH, 1,
                              1,0,0, 1,0,0, 1,0,0);
        add_ln_kernel<<<NT, 256>>>(x, tmp, agl, abl, x);

        // FFN
        tgemm_launch<false,1>(x, w1, b1l, hbuf, NT, FF, HH, HH, FF, FF, 1,
                              1,0,0, 1,0,0, 1,0,0);
        tgemm_launch<false,0>(hbuf, w2, b2l, tmp, NT, HH, FF, FF, HH, HH, 1,
                              1,0,0, 1,0,0, 1,0,0);
        add_ln_kernel<<<NT, 256>>>(x, tmp, fgl, fbl, x);
    }

    // 3) valid-token compaction
    compact_kernel<<<BB, 256>>>(x, vmask, vo);

    // 4) classifier + softmax
    cls_kernel<<<NT, 256>>>(vo, cW, cb, out);

    (void)in_sizes; (void)n_in; (void)out_size;
}

// round 5
// speedup vs baseline: 3.1088x; 2.7620x over previous
#include <cuda_runtime.h>
#include <cuda_fp16.h>
#include <math.h>
#include <stdint.h>

// ---------------- Problem constants ----------------
#define BB 16
#define SS 256
#define HH 768
#define LL 12
#define AH 12
#define DH 64
#define FF 3072
#define NL 9
#define NT (BB*SS)           // 4096 tokens
#define NBH (BB*AH)          // 192 batch*head
#define QKVN (3*HH)          // 2304

typedef long long ll;

// ---------------- Device scratch (static, allocation-free) ----------------
__device__ float g_x   [NT*HH];
__device__ float g_qkv [NT*QKVN];
__device__ float g_ctx [NT*HH];
__device__ float g_tmp [NT*HH];
__device__ float g_h   [NT*FF];
__device__ float g_sc  [(ll)NBH*SS*SS];
__device__ float g_vo  [NT*HH];
__device__ float g_bqkv[LL*QKVN];

// packed (transposed, fp16 hi/lo) weights: [L][N][K]
__device__ __half g_qkvw_h[(ll)LL*QKVN*HH];
__device__ __half g_qkvw_l[(ll)LL*QKVN*HH];
__device__ __half g_ow_h  [(ll)LL*HH*HH];
__device__ __half g_ow_l  [(ll)LL*HH*HH];
__device__ __half g_f1w_h [(ll)LL*FF*HH];
__device__ __half g_f1w_l [(ll)LL*FF*HH];
__device__ __half g_f2w_h [(ll)LL*HH*FF];
__device__ __half g_f2w_l [(ll)LL*HH*FF];
// transposed V per layer: [bh][d][s] fp16 hi/lo
__device__ __half g_vt_h  [(ll)NBH*DH*SS];
__device__ __half g_vt_l  [(ll)NBH*DH*SS];

// ---------------- PTX helpers ----------------
__device__ __forceinline__ void ldmx4(uint32_t r[4], uint32_t addr) {
    asm volatile("ldmatrix.sync.aligned.m8n8.x4.shared.b16 {%0,%1,%2,%3}, [%4];"
        : "=r"(r[0]), "=r"(r[1]), "=r"(r[2]), "=r"(r[3]) : "r"(addr));
}

__device__ __forceinline__ void mma16(float c[4], const uint32_t a[4], const uint32_t b[2]) {
    asm volatile(
        "mma.sync.aligned.m16n8k16.row.col.f32.f16.f16.f32 "
        "{%0,%1,%2,%3}, {%4,%5,%6,%7}, {%8,%9}, {%0,%1,%2,%3};"
        : "+f"(c[0]), "+f"(c[1]), "+f"(c[2]), "+f"(c[3])
        : "r"(a[0]), "r"(a[1]), "r"(a[2]), "r"(a[3]), "r"(b[0]), "r"(b[1]));
}

__device__ __forceinline__ void cpa16p(uint32_t dst, const void* src, int src_bytes) {
    asm volatile("cp.async.ca.shared.global [%0], [%1], 16, %2;"
                 :: "r"(dst), "l"(src), "r"(src_bytes));
}
__device__ __forceinline__ void cpa_commit() { asm volatile("cp.async.commit_group;"); }
__device__ __forceinline__ void cpa_wait1()  { asm volatile("cp.async.wait_group 1;"); }
__device__ __forceinline__ void cpa_wait0()  { asm volatile("cp.async.wait_group 0;"); }

// split fp32 pair -> fp16 hi pair (packed) + fp16 lo pair (packed)
__device__ __forceinline__ void split2(float x, float y, uint32_t& hp, uint32_t& lp) {
    __half hx = __float2half_rn(x), hy = __float2half_rn(y);
    __half lx = __float2half_rn(x - __half2float(hx));
    __half ly = __float2half_rn(y - __half2float(hy));
    hp = (uint32_t)__half_as_ushort(hx) | ((uint32_t)__half_as_ushort(hy) << 16);
    lp = (uint32_t)__half_as_ushort(lx) | ((uint32_t)__half_as_ushort(ly) << 16);
}

// ================= fp16 3-term tensor-core GEMM =================
// C[z] = act( A[z] @ B[z]^T (+bias) ).  A: f32 [M,K] (lda).
// B (logical [N,K]):  BPACK=1 -> pre-split fp16 hi/lo arrays (ldb = packed row len);
//                     BPACK=0 -> f32 [N,K] (ldb), converted in prefetch.
// BM=128, BN=128, BK=32, 256 threads (8 warps 2x4), warp tile 64x32.
// smem per stage 40960B: Ah@0, Al@10240, Bh@20480, Bl@30720 (pitch 80B).
#define HG_STAGE 40960
#define HG_SMEM  (2*HG_STAGE)

template<int BPACK, int ACT>
__global__ void __launch_bounds__(256)
hgemm(const float* __restrict__ A, const float* __restrict__ Bf,
      const __half* __restrict__ Bph, const __half* __restrict__ Bpl,
      const float* __restrict__ bias, float* __restrict__ C,
      int M, int N, int K, int lda, int ldb, int ldc,
      int divA, ll sA1, ll sA2,
      int divB, ll sB1, ll sB2,
      int divC, ll sC1, ll sC2)
{
    extern __shared__ char sm[];
    const int tid = threadIdx.x;
    const int lane = tid & 31;
    const int wid = tid >> 5;
    const int wm = wid & 1;        // 2 warps in M
    const int wn = wid >> 1;       // 4 warps in N
    const int z = blockIdx.z;
    const int tm0 = blockIdx.y * 128;
    const int tn0 = blockIdx.x * 128;

    const float* Ab = A + (ll)(z / divA) * sA1 + (ll)(z % divA) * sA2 + (ll)tm0 * lda;
    const float* Bb = nullptr;
    const __half *Wh = nullptr, *Wl = nullptr;
    if (BPACK) {
        Wh = Bph + (ll)(z / divB) * sB1 + (ll)(z % divB) * sB2;
        Wl = Bpl + (ll)(z / divB) * sB1 + (ll)(z % divB) * sB2;
    } else {
        Bb = Bf + (ll)(z / divB) * sB1 + (ll)(z % divB) * sB2;
    }
    float* Cb = C + (ll)(z / divC) * sC1 + (ll)(z % divC) * sC2;

    uint32_t sbase = (uint32_t)__cvta_generic_to_shared(sm);

    float acc[16][4];
    #pragma unroll
    for (int i = 0; i < 16; i++)
        #pragma unroll
        for (int q = 0; q < 4; q++) acc[i][q] = 0.f;

    auto prefetch = [&](int kt, int s) {
        char* stc = sm + s * HG_STAGE;
        // ---- A: 128 x 32 f32 -> fp16 hi/lo smem ----
        const float* As0 = Ab + kt * 32;
        #pragma unroll
        for (int j = 0; j < 4; j++) {
            int c = tid + j * 256;             // 0..1023
            int row = c >> 3, kq = c & 7;
            float4 v = *(const float4*)(As0 + (ll)row * lda + kq * 4);
            uint2 hv, lv;
            split2(v.x, v.y, hv.x, lv.x);
            split2(v.z, v.w, hv.y, lv.y);
            int off = row * 80 + kq * 8;
            *(uint2*)(stc + off) = hv;
            *(uint2*)(stc + 10240 + off) = lv;
        }
        if (BPACK) {
            // ---- B: cp.async 16B chunks of pre-split fp16 ----
            uint32_t std = sbase + s * HG_STAGE + 20480;
            #pragma unroll
            for (int j = 0; j < 2; j++) {
                int c = tid + j * 256;         // 0..511
                int row = c >> 2, kc = c & 3;
                int n = tn0 + row;
                bool ok = n < N;
                const __half* srcH = ok ? (Wh + (ll)n * ldb + kt * 32 + kc * 8) : Wh;
                const __half* srcL = ok ? (Wl + (ll)n * ldb + kt * 32 + kc * 8) : Wl;
                uint32_t d0 = std + row * 80 + kc * 16;
                cpa16p(d0,         srcH, ok ? 16 : 0);
                cpa16p(d0 + 10240, srcL, ok ? 16 : 0);
            }
            cpa_commit();
        } else {
            // ---- B: f32 [N,K] -> fp16 hi/lo smem ----
            char* stb = stc + 20480;
            #pragma unroll
            for (int j = 0; j < 4; j++) {
                int c = tid + j * 256;
                int row = c >> 3, kq = c & 7;
                int n = tn0 + row;
                float4 v = (n < N) ? *(const float4*)(Bb + (ll)n * ldb + kt * 32 + kq * 4)
                                   : make_float4(0.f, 0.f, 0.f, 0.f);
                uint2 hv, lv;
                split2(v.x, v.y, hv.x, lv.x);
                split2(v.z, v.w, hv.y, lv.y);
                int off = row * 80 + kq * 8;
                *(uint2*)(stb + off) = hv;
                *(uint2*)(stb + 10240 + off) = lv;
            }
        }
    };

    const int KT = K / 32;
    prefetch(0, 0);

    // per-lane ldmatrix address components
    const int arb = (lane & 7) + ((lane >> 3) & 1) * 8;   // A row within 16
    const int akh = (lane >> 4) * 16;                     // A k-half bytes
    const int bq  = lane >> 3;
    const int bnb = ((bq >> 1) << 3) + (lane & 7);        // B n within 16
    const int bkh = (bq & 1) * 16;                        // B k-half bytes

    for (int kt = 0; kt < KT; kt++) {
        const int s = kt & 1;
        if (kt + 1 < KT) { prefetch(kt + 1, s ^ 1); if (BPACK) cpa_wait1(); }
        else             { if (BPACK) cpa_wait0(); }
        __syncthreads();

        uint32_t stA = sbase + s * HG_STAGE;
        uint32_t stB = stA + 20480;

        #pragma unroll
        for (int ks = 0; ks < 2; ks++) {
            uint32_t ah[4][4], al[4][4], bh[4][2], bl[4][2];
            #pragma unroll
            for (int mt = 0; mt < 4; mt++) {
                uint32_t ad = stA + (wm * 64 + mt * 16 + arb) * 80 + ks * 32 + akh;
                ldmx4(ah[mt], ad);
                ldmx4(al[mt], ad + 10240);
            }
            #pragma unroll
            for (int p = 0; p < 2; p++) {
                uint32_t bd = stB + (wn * 32 + p * 16 + bnb) * 80 + ks * 32 + bkh;
                uint32_t r[4];
                ldmx4(r, bd);
                bh[p*2][0] = r[0]; bh[p*2][1] = r[1]; bh[p*2+1][0] = r[2]; bh[p*2+1][1] = r[3];
                ldmx4(r, bd + 10240);
                bl[p*2][0] = r[0]; bl[p*2][1] = r[1]; bl[p*2+1][0] = r[2]; bl[p*2+1][1] = r[3];
            }
            #pragma unroll
            for (int mt = 0; mt < 4; mt++)
                #pragma unroll
                for (int nt = 0; nt < 4; nt++) mma16(acc[mt*4+nt], ah[mt], bh[nt]);
            #pragma unroll
            for (int mt = 0; mt < 4; mt++)
                #pragma unroll
                for (int nt = 0; nt < 4; nt++) mma16(acc[mt*4+nt], al[mt], bh[nt]);
            #pragma unroll
            for (int mt = 0; mt < 4; mt++)
                #pragma unroll
                for (int nt = 0; nt < 4; nt++) mma16(acc[mt*4+nt], ah[mt], bl[nt]);
        }
        __syncthreads();
    }

    // ---- epilogue ----
    #pragma unroll
    for (int mt = 0; mt < 4; mt++) {
        int r0 = tm0 + wm * 64 + mt * 16 + (lane >> 2);
        #pragma unroll
        for (int nt = 0; nt < 4; nt++) {
            int col = tn0 + wn * 32 + nt * 8 + 2 * (lane & 3);
            if (col < N) {
                float v0 = acc[mt*4+nt][0], v1 = acc[mt*4+nt][1];
                float v2 = acc[mt*4+nt][2], v3 = acc[mt*4+nt][3];
                if (bias) {
                    float2 b2 = *(const float2*)(bias + col);
                    v0 += b2.x; v1 += b2.y; v2 += b2.x; v3 += b2.y;
                }
                if (ACT == 1) {
                    float t;
                    t = v0; v0 = 0.5f*t*(1.f + tanhf(0.7978845608028654f*(t + 0.044715f*t*t*t)));
                    t = v1; v1 = 0.5f*t*(1.f + tanhf(0.7978845608028654f*(t + 0.044715f*t*t*t)));
                    t = v2; v2 = 0.5f*t*(1.f + tanhf(0.7978845608028654f*(t + 0.044715f*t*t*t)));
                    t = v3; v3 = 0.5f*t*(1.f + tanhf(0.7978845608028654f*(t + 0.044715f*t*t*t)));
                }
                *(float2*)&Cb[(ll)r0 * ldc + col]       = make_float2(v0, v1);
                *(float2*)&Cb[(ll)(r0 + 8) * ldc + col] = make_float2(v2, v3);
            }
        }
    }
}

template<int BPACK, int ACT>
static void hgemm_launch(const float* A, const float* Bf, const __half* Wh, const __half* Wl,
                         const float* bias, float* C,
                         int M, int N, int K, int lda, int ldb, int ldc, int batches,
                         int divA, ll sA1, ll sA2,
                         int divB, ll sB1, ll sB2,
                         int divC, ll sC1, ll sC2)
{
    dim3 grid((N + 127) / 128, M / 128, batches);
    hgemm<BPACK, ACT><<<grid, 256, HG_SMEM>>>(A, Bf, Wh, Wl, bias, C, M, N, K, lda, ldb, ldc,
                                              divA, sA1, sA2, divB, sB1, sB2, divC, sC1, sC2);
}

// ================= weight packing (transpose + fp16 split) =================
__global__ void pack_w_kernel(const float* __restrict__ W, __half* __restrict__ Ph,
                              __half* __restrict__ Pl, int K, int N)
{
    __shared__ float t[32][33];
    int l = blockIdx.z;
    const float* Wb = W + (ll)l * K * N;
    __half* Phb = Ph + (ll)l * N * K;
    __half* Plb = Pl + (ll)l * N * K;
    int k0 = blockIdx.x * 32, n0 = blockIdx.y * 32;
    int tx = threadIdx.x, ty = threadIdx.y;
    #pragma unroll
    for (int j = 0; j < 4; j++)
        t[ty + j * 8][tx] = Wb[(ll)(k0 + ty + j * 8) * N + n0 + tx];
    __syncthreads();
    #pragma unroll
    for (int j = 0; j < 4; j++) {
        int n = n0 + ty + j * 8, k = k0 + tx;
        float v = t[tx][ty + j * 8];
        __half h = __float2half_rn(v);
        __half lo = __float2half_rn(v - __half2float(h));
        Phb[(ll)n * K + k] = h;
        Plb[(ll)n * K + k] = lo;
    }
}

__global__ void pack_qkvw_kernel(const float* __restrict__ Wq, const float* __restrict__ Wk,
                                 const float* __restrict__ Wv,
                                 __half* __restrict__ Ph, __half* __restrict__ Pl)
{
    __shared__ float t[32][33];
    int l = blockIdx.z;
    int k0 = blockIdx.x * 32, n0 = blockIdx.y * 32;
    int sel = n0 / HH;
    const float* Wb = ((sel == 0) ? Wq : (sel == 1) ? Wk : Wv) + (ll)l * HH * HH;
    int nc0 = n0 - sel * HH;
    __half* Phb = Ph + (ll)l * QKVN * HH;
    __half* Plb = Pl + (ll)l * QKVN * HH;
    int tx = threadIdx.x, ty = threadIdx.y;
    #pragma unroll
    for (int j = 0; j < 4; j++)
        t[ty + j * 8][tx] = Wb[(ll)(k0 + ty + j * 8) * HH + nc0 + tx];
    __syncthreads();
    #pragma unroll
    for (int j = 0; j < 4; j++) {
        int n = n0 + ty + j * 8, k = k0 + tx;
        float v = t[tx][ty + j * 8];
        __half h = __float2half_rn(v);
        __half lo = __float2half_rn(v - __half2float(h));
        Phb[(ll)n * HH + k] = h;
        Plb[(ll)n * HH + k] = lo;
    }
}

__global__ void pack_bias_kernel(const float* __restrict__ bq, const float* __restrict__ bk,
                                 const float* __restrict__ bv, float* __restrict__ bp)
{
    int i = blockIdx.x * 256 + threadIdx.x;
    if (i >= LL * QKVN) return;
    int l = i / QKVN, col = i % QKVN;
    int sel = col / HH, cc = col % HH;
    const float* b = (sel == 0) ? bq : (sel == 1) ? bk : bv;
    bp[i] = b[l * HH + cc];
}

// ---- V transpose + fp16 split: qkv V slice [s][d] -> Vt [bh][d][s] ----
__global__ void vtrans_kernel(const float* __restrict__ qkv,
                              __half* __restrict__ Vh, __half* __restrict__ Vl)
{
    __shared__ float t[32][33];
    int s0 = blockIdx.x * 32;
    int d0 = blockIdx.y * 32;
    int bh = blockIdx.z;
    int b = bh / AH, h = bh % AH;
    const float* src = qkv + (ll)(b * SS) * QKVN + 2 * HH + h * DH;
    int tx = threadIdx.x, ty = threadIdx.y;
    #pragma unroll
    for (int j = 0; j < 4; j++)
        t[ty + j * 8][tx] = src[(ll)(s0 + ty + j * 8) * QKVN + d0 + tx];
    __syncthreads();
    __half* Vhb = Vh + (ll)bh * DH * SS;
    __half* Vlb = Vl + (ll)bh * DH * SS;
    #pragma unroll
    for (int j = 0; j < 4; j++) {
        int d = d0 + ty + j * 8, sidx = s0 + tx;
        float v = t[tx][ty + j * 8];
        __half hh = __float2half_rn(v);
        __half lo = __float2half_rn(v - __half2float(hh));
        Vhb[(ll)d * SS + sidx] = hh;
        Vlb[(ll)d * SS + sidx] = lo;
    }
}

// ================= block reduction =================
template<bool MAXR>
__device__ __forceinline__ float block_reduce(float v) {
    __shared__ float sh[33];
    int lane = threadIdx.x & 31, w = threadIdx.x >> 5;
    #pragma unroll
    for (int o = 16; o; o >>= 1) {
        float t = __shfl_xor_sync(0xffffffffu, v, o);
        v = MAXR ? fmaxf(v, t) : (v + t);
    }
    if (lane == 0) sh[w] = v;
    __syncthreads();
    if (w == 0) {
        int nw = blockDim.x >> 5;
        float t = (lane < nw) ? sh[lane] : (MAXR ? -3.4e38f : 0.f);
        #pragma unroll
        for (int o = 16; o; o >>= 1) {
            float u = __shfl_xor_sync(0xffffffffu, t, o);
            t = MAXR ? fmaxf(t, u) : (t + u);
        }
        if (lane == 0) sh[32] = t;
    }
    __syncthreads();
    float r = sh[32];
    __syncthreads();
    return r;
}

// ================= elementwise kernels =================
__global__ void embed_ln_kernel(const int* __restrict__ ids, const int* __restrict__ types,
                                const float* __restrict__ wemb, const float* __restrict__ pemb,
                                const float* __restrict__ temb,
                                const float* __restrict__ g, const float* __restrict__ b,
                                float* __restrict__ x)
{
    int tok = blockIdx.x;
    int s = tok % SS;
    int t = threadIdx.x;
    int id = ids[tok];
    int ty = types[tok];
    float v[3];
    float sum = 0.f;
    #pragma unroll
    for (int i = 0; i < 3; i++) {
        int h = t + i*256;
        float val = wemb[(ll)id*HH + h] + pemb[s*HH + h] + temb[ty*HH + h];
        v[i] = val; sum += val;
    }
    float mean = block_reduce<false>(sum) * (1.f/HH);
    float sq = 0.f;
    #pragma unroll
    for (int i = 0; i < 3; i++) { float d = v[i] - mean; sq += d*d; }
    float var = block_reduce<false>(sq) * (1.f/HH);
    float rstd = rsqrtf(var + 1e-12f);
    #pragma unroll
    for (int i = 0; i < 3; i++) {
        int h = t + i*256;
        x[(ll)tok*HH + h] = (v[i] - mean) * rstd * g[h] + b[h];
    }
}

__global__ void add_ln_kernel(const float* __restrict__ xin, const float* __restrict__ tmp,
                              const float* __restrict__ g, const float* __restrict__ b,
                              float* __restrict__ xout)
{
    int tok = blockIdx.x;
    int t = threadIdx.x;
    float v[3];
    float sum = 0.f;
    #pragma unroll
    for (int i = 0; i < 3; i++) {
        int h = t + i*256;
        float val = xin[(ll)tok*HH + h] + tmp[(ll)tok*HH + h];
        v[i] = val; sum += val;
    }
    float mean = block_reduce<false>(sum) * (1.f/HH);
    float sq = 0.f;
    #pragma unroll
    for (int i = 0; i < 3; i++) { float d = v[i] - mean; sq += d*d; }
    float var = block_reduce<false>(sq) * (1.f/HH);
    float rstd = rsqrtf(var + 1e-12f);
    #pragma unroll
    for (int i = 0; i < 3; i++) {
        int h = t + i*256;
        xout[(ll)tok*HH + h] = (v[i] - mean) * rstd * g[h] + b[h];
    }
}

__global__ void attn_softmax_kernel(float* __restrict__ sc, const int* __restrict__ mask)
{
    ll row = blockIdx.x;
    int t = threadIdx.x;
    int bh = (int)(row >> 8);
    int b = bh / AH;
    float* p = sc + row * SS;
    float madd = mask[b*SS + t] ? 0.f : -10000.f;
    float v = p[t] * 0.125f + madd;
    float mx = block_reduce<true>(v);
    float e = expf(v - mx);
    float s = block_reduce<false>(e);
    p[t] = e / s;
}

__global__ void compact_kernel(const float* __restrict__ x, const int* __restrict__ valid,
                               float* __restrict__ vo)
{
    int b = blockIdx.x;
    int t = threadIdx.x;
    __shared__ int vload[SS];
    __shared__ int rank[SS];
    vload[t] = valid[b*SS + t];
    __syncthreads();
    int r = 0;
    for (int i = 0; i < t; i++) r += vload[i];
    rank[t] = r;
    __syncthreads();
    float* vob = vo + (ll)b * SS * HH;
    for (int i = t; i < SS*HH; i += 256) vob[i] = 0.f;
    __syncthreads();
    int w = t >> 5, lane = t & 31;
    for (int s = w; s < SS; s += 8) {
        if (vload[s]) {
            const float* src = x + ((ll)b*SS + s) * HH;
            float* dst = vob + (ll)rank[s] * HH;
            for (int i = lane; i < HH; i += 32) dst[i] = src[i];
        }
    }
}

__global__ void cls_kernel(const float* __restrict__ vo, const float* __restrict__ W,
                           const float* __restrict__ bias, float* __restrict__ out)
{
    int tok = blockIdx.x;
    int t = threadIdx.x;
    const float* v = vo + (ll)tok * HH;
    float acc[NL];
    #pragma unroll
    for (int j = 0; j < NL; j++) acc[j] = 0.f;
    for (int i = t; i < HH; i += 256) {
        float xv = v[i];
        const float* w = W + (ll)i * NL;
        #pragma unroll
        for (int j = 0; j < NL; j++) acc[j] += xv * w[j];
    }
    __shared__ float red[NL*256];
    #pragma unroll
    for (int j = 0; j < NL; j++) red[j*256 + t] = acc[j];
    __syncthreads();
    for (int o = 128; o; o >>= 1) {
        if (t < o) {
            #pragma unroll
            for (int j = 0; j < NL; j++) red[j*256 + t] += red[j*256 + t + o];
        }
        __syncthreads();
    }
    if (t == 0) {
        float lg[NL];
        float mx = -3.4e38f;
        #pragma unroll
        for (int j = 0; j < NL; j++) { lg[j] = red[j*256] + bias[j]; mx = fmaxf(mx, lg[j]); }
        float s = 0.f;
        #pragma unroll
        for (int j = 0; j < NL; j++) { lg[j] = expf(lg[j] - mx); s += lg[j]; }
        float inv = 1.f / s;
        #pragma unroll
        for (int j = 0; j < NL; j++) out[(ll)tok*NL + j] = lg[j] * inv;
    }
}

// ================= launch orchestration =================
extern "C" void kernel_launch(void* const* d_in, const int* in_sizes, int n_in,
                              void* d_out, int out_size)
{
    const int*   ids   = (const int*)  d_in[0];
    const int*   imask = (const int*)  d_in[1];
    const int*   types = (const int*)  d_in[2];
    const int*   vmask = (const int*)  d_in[3];
    const float* wemb  = (const float*)d_in[4];
    const float* pemb  = (const float*)d_in[5];
    const float* temb  = (const float*)d_in[6];
    const float* eg    = (const float*)d_in[7];
    const float* eb    = (const float*)d_in[8];
    const float* Wq    = (const float*)d_in[9];
    const float* bq    = (const float*)d_in[10];
    const float* Wk    = (const float*)d_in[11];
    const float* bk    = (const float*)d_in[12];
    const float* Wv    = (const float*)d_in[13];
    const float* bv    = (const float*)d_in[14];
    const float* Wo    = (const float*)d_in[15];
    const float* bo    = (const float*)d_in[16];
    const float* ag    = (const float*)d_in[17];
    const float* ab    = (const float*)d_in[18];
    const float* W1    = (const float*)d_in[19];
    const float* b1    = (const float*)d_in[20];
    const float* W2    = (const float*)d_in[21];
    const float* b2    = (const float*)d_in[22];
    const float* fg    = (const float*)d_in[23];
    const float* fb    = (const float*)d_in[24];
    const float* cW    = (const float*)d_in[25];
    const float* cb    = (const float*)d_in[26];
    float* out = (float*)d_out;

    float *x, *qkv, *ctx, *tmp, *hbuf, *sc, *vo, *bqkv;
    __half *qkvw_h, *qkvw_l, *ow_h, *ow_l, *f1w_h, *f1w_l, *f2w_h, *f2w_l, *vt_h, *vt_l;
    cudaGetSymbolAddress((void**)&x,    g_x);
    cudaGetSymbolAddress((void**)&qkv,  g_qkv);
    cudaGetSymbolAddress((void**)&ctx,  g_ctx);
    cudaGetSymbolAddress((void**)&tmp,  g_tmp);
    cudaGetSymbolAddress((void**)&hbuf, g_h);
    cudaGetSymbolAddress((void**)&sc,   g_sc);
    cudaGetSymbolAddress((void**)&vo,   g_vo);
    cudaGetSymbolAddress((void**)&bqkv, g_bqkv);
    cudaGetSymbolAddress((void**)&qkvw_h, g_qkvw_h);
    cudaGetSymbolAddress((void**)&qkvw_l, g_qkvw_l);
    cudaGetSymbolAddress((void**)&ow_h,   g_ow_h);
    cudaGetSymbolAddress((void**)&ow_l,   g_ow_l);
    cudaGetSymbolAddress((void**)&f1w_h,  g_f1w_h);
    cudaGetSymbolAddress((void**)&f1w_l,  g_f1w_l);
    cudaGetSymbolAddress((void**)&f2w_h,  g_f2w_h);
    cudaGetSymbolAddress((void**)&f2w_l,  g_f2w_l);
    cudaGetSymbolAddress((void**)&vt_h,   g_vt_h);
    cudaGetSymbolAddress((void**)&vt_l,   g_vt_l);

    cudaFuncSetAttribute(hgemm<1,0>, cudaFuncAttributeMaxDynamicSharedMemorySize, HG_SMEM);
    cudaFuncSetAttribute(hgemm<1,1>, cudaFuncAttributeMaxDynamicSharedMemorySize, HG_SMEM);
    cudaFuncSetAttribute(hgemm<0,0>, cudaFuncAttributeMaxDynamicSharedMemorySize, HG_SMEM);

    // 0) pack weights: transpose to [N][K], split fp16 hi/lo
    {
        dim3 blk(32, 8);
        pack_qkvw_kernel<<<dim3(HH/32, QKVN/32, LL), blk>>>(Wq, Wk, Wv, qkvw_h, qkvw_l);
        pack_w_kernel<<<dim3(HH/32, HH/32, LL),  blk>>>(Wo, ow_h,  ow_l,  HH, HH);
        pack_w_kernel<<<dim3(HH/32, FF/32, LL),  blk>>>(W1, f1w_h, f1w_l, HH, FF);
        pack_w_kernel<<<dim3(FF/32, HH/32, LL),  blk>>>(W2, f2w_h, f2w_l, FF, HH);
        pack_bias_kernel<<<(LL*QKVN + 255)/256, 256>>>(bq, bk, bv, bqkv);
    }

    // 1) embeddings + LN
    embed_ln_kernel<<<NT, 256>>>(ids, types, wemb, pemb, temb, eg, eb, x);

    // 2) transformer layers
    for (int l = 0; l < LL; l++) {
        const float* bol = bo + (ll)l*HH;
        const float* b1l = b1 + (ll)l*FF;
        const float* b2l = b2 + (ll)l*HH;
        const float* agl = ag + (ll)l*HH;    const float* abl = ab + (ll)l*HH;
        const float* fgl = fg + (ll)l*HH;    const float* fbl = fb + (ll)l*HH;

        // fused QKV projection
        hgemm_launch<1,0>(x, nullptr, qkvw_h + (ll)l*QKVN*HH, qkvw_l + (ll)l*QKVN*HH,
                          bqkv + (ll)l*QKVN, qkv, NT, QKVN, HH, HH, HH, QKVN, 1,
                          1,0,0, 1,0,0, 1,0,0);

        // V transpose + split
        vtrans_kernel<<<dim3(SS/32, DH/32, NBH), dim3(32, 8)>>>(qkv, vt_h, vt_l);

        // scores = Q * K^T per (b,h):  A = Q view, B = K view (f32 convert path)
        hgemm_launch<0,0>(qkv, qkv + HH, nullptr, nullptr, nullptr, sc,
                          SS, SS, DH, QKVN, QKVN, SS, NBH,
                          AH, (ll)SS*QKVN, DH,
                          AH, (ll)SS*QKVN, DH,
                          1,  (ll)SS*SS, 0);
        attn_softmax_kernel<<<NBH*SS, 256>>>(sc, imask);

        // ctx = P * V per (b,h):  B = pre-transposed V (packed path), N = 64
        hgemm_launch<1,0>(sc, nullptr, vt_h, vt_l, nullptr, ctx,
                          SS, DH, SS, SS, SS, HH, NBH,
                          1,  (ll)SS*SS, 0,
                          1,  (ll)DH*SS, 0,
                          AH, (ll)SS*HH, DH);

        // output projection
        hgemm_launch<1,0>(ctx, nullptr, ow_h + (ll)l*HH*HH, ow_l + (ll)l*HH*HH,
                          bol, tmp, NT, HH, HH, HH, HH, HH, 1,
                          1,0,0, 1,0,0, 1,0,0);
        add_ln_kernel<<<NT, 256>>>(x, tmp, agl, abl, x);

        // FFN
        hgemm_launch<1,1>(x, nullptr, f1w_h + (ll)l*FF*HH, f1w_l + (ll)l*FF*HH,
                          b1l, hbuf, NT, FF, HH, HH, HH, FF, 1,
                          1,0,0, 1,0,0, 1,0,0);
        hgemm_launch<1,0>(hbuf, nullptr, f2w_h + (ll)l*HH*FF, f2w_l + (ll)l*HH*FF,
                          b2l, tmp, NT, HH, FF, FF, FF, HH, 1,
                          1,0,0, 1,0,0, 1,0,0);
        add_ln_kernel<<<NT, 256>>>(x, tmp, fgl, fbl, x);
    }

    // 3) valid-token compaction
    compact_kernel<<<BB, 256>>>(x, vmask, vo);

    // 4) classifier + softmax
    cls_kernel<<<NT, 256>>>(vo, cW, cb, out);

    (void)in_sizes; (void)n_in; (void)out_size;
}